// round 8
// baseline (speedup 1.0000x reference)
#include <cuda_runtime.h>
#include <cuda_fp16.h>

#define NN 100000
#define NE 3200000
#define C1 256
#define C2 64
#define C3 128
#define NBLK ((NN + 255) / 256)   // 391

// Scratch (static device globals — no allocation allowed)
__device__ __half2 g_hs1h[(size_t)NN * C2 / 2];  // dinv * (x @ W1), fp16
__device__ __half2 g_rs1h[(size_t)NN * C2 / 2];  // dinv * relu(dinv*agg1 + b1), fp16
__device__ float   g_a2[(size_t)NN * C2];        // dinv * layer2 aggregate (fp32)
__device__ int     g_deg[NN];
__device__ float   g_dinv[NN];
__device__ float   g_gsum[C3];
// CSR of in-edges
__device__ int   g_off[NN + 1];
__device__ int   g_cur[NN];
__device__ int   g_csrc[NE];
__device__ int   g_bsum[512];
__device__ int   g_bpre[512];

// ---------------- degree / norm ----------------
__global__ void deginit_k() {
    int i = blockIdx.x * blockDim.x + threadIdx.x;
    if (i < NN) g_deg[i] = 1;          // self loop
    if (i < C3) g_gsum[i] = 0.f;
}

__global__ void degcnt_k(const int* __restrict__ ei) {
    int e = blockIdx.x * blockDim.x + threadIdx.x;
    if (e < NE) atomicAdd(&g_deg[ei[NE + e]], 1);
}

__global__ void dinv_k() {
    int i = blockIdx.x * blockDim.x + threadIdx.x;
    if (i < NN) g_dinv[i] = rsqrtf((float)g_deg[i]);
}

// ---------------- CSR build: scan of (deg-1), then cursor fill ----------------
__global__ void scanA_k() {      // per-block sums
    __shared__ int sm[256];
    int i = blockIdx.x * 256 + threadIdx.x;
    sm[threadIdx.x] = (i < NN) ? (g_deg[i] - 1) : 0;
    __syncthreads();
    for (int o = 128; o; o >>= 1) {
        if (threadIdx.x < o) sm[threadIdx.x] += sm[threadIdx.x + o];
        __syncthreads();
    }
    if (threadIdx.x == 0) g_bsum[blockIdx.x] = sm[0];
}

__global__ void scanB_k() {      // exclusive scan of block sums (1 block, 512 thr)
    __shared__ int sm[512];
    int t = threadIdx.x;
    int v = (t < NBLK) ? g_bsum[t] : 0;
    sm[t] = v;
    __syncthreads();
    for (int o = 1; o < 512; o <<= 1) {
        int add = (t >= o) ? sm[t - o] : 0;
        __syncthreads();
        sm[t] += add;
        __syncthreads();
    }
    if (t < NBLK) g_bpre[t] = sm[t] - v;
}

__global__ void scanC_k() {      // intra-block exclusive scan + base -> offsets
    __shared__ int sm[256];
    int t = threadIdx.x;
    int i = blockIdx.x * 256 + t;
    int v = (i < NN) ? (g_deg[i] - 1) : 0;
    sm[t] = v;
    __syncthreads();
    for (int o = 1; o < 256; o <<= 1) {
        int add = (t >= o) ? sm[t - o] : 0;
        __syncthreads();
        sm[t] += add;
        __syncthreads();
    }
    if (i < NN) {
        int off = g_bpre[blockIdx.x] + sm[t] - v;
        g_off[i] = off;
        g_cur[i] = off;
    }
    if (i == 0) g_off[NN] = NE;
}

__global__ void fill_k(const int* __restrict__ ei) {
    int e = blockIdx.x * blockDim.x + threadIdx.x;
    if (e >= NE) return;
    int s = ei[e];
    int d = ei[NE + e];
    int pos = atomicAdd(&g_cur[d], 1);
    g_csrc[pos] = s;
}

// ---------------- GEMM1: hs1 = fp16(dinv * (x @ W1)) ----------------
__global__ void gemm1_k(const float* __restrict__ x, const float* __restrict__ W1) {
    __shared__ float xs[64][68];
    __shared__ float ws[64][68];
    int row0 = blockIdx.x * 64;
    int tid = threadIdx.x;
    int ty = tid >> 4, tx = tid & 15;
    float acc[4][4];
#pragma unroll
    for (int i = 0; i < 4; i++)
#pragma unroll
        for (int j = 0; j < 4; j++) acc[i][j] = 0.f;

    for (int kc = 0; kc < C1; kc += 64) {
#pragma unroll
        for (int i = 0; i < 4; i++) {
            int li = tid + i * 256;            // float4 index 0..1023
            int r = li >> 4, c4 = li & 15;
            int grow = row0 + r;
            float4 v = make_float4(0.f, 0.f, 0.f, 0.f);
            if (grow < NN) v = *(const float4*)(x + (size_t)grow * C1 + kc + c4 * 4);
            *(float4*)&xs[r][c4 * 4] = v;
        }
#pragma unroll
        for (int i = 0; i < 4; i++) {
            int li = tid + i * 256;
            int r = li >> 4, c4 = li & 15;
            *(float4*)&ws[r][c4 * 4] = *(const float4*)(W1 + (size_t)(kc + r) * C2 + c4 * 4);
        }
        __syncthreads();
#pragma unroll
        for (int k = 0; k < 64; k++) {
            float a[4], b[4];
#pragma unroll
            for (int i = 0; i < 4; i++) a[i] = xs[ty * 4 + i][k];
#pragma unroll
            for (int j = 0; j < 4; j++) b[j] = ws[k][tx * 4 + j];
#pragma unroll
            for (int i = 0; i < 4; i++)
#pragma unroll
                for (int j = 0; j < 4; j++) acc[i][j] += a[i] * b[j];
        }
        __syncthreads();
    }
#pragma unroll
    for (int i = 0; i < 4; i++) {
        int grow = row0 + ty * 4 + i;
        if (grow < NN) {
            float dv = g_dinv[grow];
            __half2 h0 = __floats2half2_rn(acc[i][0] * dv, acc[i][1] * dv);
            __half2 h1 = __floats2half2_rn(acc[i][2] * dv, acc[i][3] * dv);
            g_hs1h[(size_t)grow * 32 + tx * 2]     = h0;
            g_hs1h[(size_t)grow * 32 + tx * 2 + 1] = h1;
        }
    }
}

// ------------- pull layer1: warp per node, fp16 gather, fp32 accumulate -------------
// rs1[d] = fp16( dinv_d * relu(dinv_d * (hs1[d] + sum_in hs1[s]) + b1) )
__global__ void pull1_k(const float* __restrict__ b1) {
    int w = (blockIdx.x * blockDim.x + threadIdx.x) >> 5;
    if (w >= NN) return;
    int lane = threadIdx.x & 31;
    int beg = g_off[w], end = g_off[w + 1];
    float2 acc = __half22float2(g_hs1h[(size_t)w * 32 + lane]);   // self loop
    int i = beg;
    while (i < end) {
        int n = end - i; if (n > 32) n = 32;
        int idx = 0;
        if (lane < n) idx = __ldg(g_csrc + i + lane);
#pragma unroll 4
        for (int j = 0; j < n; j++) {
            int s = __shfl_sync(0xffffffffu, idx, j);
            float2 v = __half22float2(g_hs1h[(size_t)s * 32 + lane]);
            acc.x += v.x; acc.y += v.y;
        }
        i += n;
    }
    float dv = g_dinv[w];
    float2 bb = *((const float2*)b1 + lane);
    acc.x = fmaxf(acc.x * dv + bb.x, 0.f) * dv;
    acc.y = fmaxf(acc.y * dv + bb.y, 0.f) * dv;
    g_rs1h[(size_t)w * 32 + lane] = __floats2half2_rn(acc.x, acc.y);
}

// ------------- pull layer2: a2[d] = dinv_d * (rs1[d] + sum_in rs1[s]) -------------
__global__ void pull2_k() {
    int w = (blockIdx.x * blockDim.x + threadIdx.x) >> 5;
    if (w >= NN) return;
    int lane = threadIdx.x & 31;
    int beg = g_off[w], end = g_off[w + 1];
    float2 acc = __half22float2(g_rs1h[(size_t)w * 32 + lane]);   // self loop
    int i = beg;
    while (i < end) {
        int n = end - i; if (n > 32) n = 32;
        int idx = 0;
        if (lane < n) idx = __ldg(g_csrc + i + lane);
#pragma unroll 4
        for (int j = 0; j < n; j++) {
            int s = __shfl_sync(0xffffffffu, idx, j);
            float2 v = __half22float2(g_rs1h[(size_t)s * 32 + lane]);
            acc.x += v.x; acc.y += v.y;
        }
        i += n;
    }
    float dv = g_dinv[w];
    acc.x *= dv; acc.y *= dv;
    *((float2*)(g_a2 + (size_t)w * C2) + lane) = acc;
}

// --------- GEMM2 + mean fused: gsum += colsum(relu(a2 @ W2 + b2)) ---------
__global__ void gemm2mean_k(const float* __restrict__ W2, const float* __restrict__ b2) {
    __shared__ float xs[64][64];
    __shared__ float ws[64][128];
    __shared__ float rsm[16][132];
    int row0 = blockIdx.x * 64;
    int tid = threadIdx.x;
    int ty = tid >> 4, tx = tid & 15;

#pragma unroll
    for (int i = 0; i < 8; i++) {
        int li = tid + i * 256;            // 32 float4 per row
        int r = li >> 5, c4 = li & 31;
        *(float4*)&ws[r][c4 * 4] = *(const float4*)(W2 + (size_t)r * C3 + c4 * 4);
    }
#pragma unroll
    for (int i = 0; i < 4; i++) {
        int li = tid + i * 256;            // 16 float4 per row
        int r = li >> 4, c4 = li & 15;
        int grow = row0 + r;
        float4 v = make_float4(0.f, 0.f, 0.f, 0.f);
        if (grow < NN) v = *(const float4*)(g_a2 + (size_t)grow * C2 + c4 * 4);
        *(float4*)&xs[r][c4 * 4] = v;
    }
    __syncthreads();

    float acc[4][8];
#pragma unroll
    for (int i = 0; i < 4; i++)
#pragma unroll
        for (int j = 0; j < 8; j++) acc[i][j] = 0.f;

#pragma unroll
    for (int k = 0; k < 64; k++) {
        float a[4], b[8];
#pragma unroll
        for (int i = 0; i < 4; i++) a[i] = xs[ty * 4 + i][k];
#pragma unroll
        for (int j = 0; j < 8; j++) b[j] = ws[k][tx * 8 + j];
#pragma unroll
        for (int i = 0; i < 4; i++)
#pragma unroll
            for (int j = 0; j < 8; j++) acc[i][j] += a[i] * b[j];
    }

    float part[8];
#pragma unroll
    for (int j = 0; j < 8; j++) {
        float bias = b2[tx * 8 + j];
        float s = 0.f;
#pragma unroll
        for (int i = 0; i < 4; i++) {
            int grow = row0 + ty * 4 + i;
            if (grow < NN) s += fmaxf(acc[i][j] + bias, 0.f);
        }
        part[j] = s;
    }
#pragma unroll
    for (int j = 0; j < 8; j++) rsm[ty][tx * 8 + j] = part[j];
    __syncthreads();

    if (tid < C3) {
        float s = 0.f;
#pragma unroll
        for (int r = 0; r < 16; r++) s += rsm[r][tid];
        atomicAdd(&g_gsum[tid], s);
    }
}

// ---------------- final FC: out[k] = (gsum/N) . fcW[k] + fcb[k] ----------------
__global__ void fc_k(const float* __restrict__ fcW, const float* __restrict__ fcb,
                     float* __restrict__ out) {
    int k = threadIdx.x >> 5, lane = threadIdx.x & 31;
    float s = 0.f;
    for (int f = lane; f < C3; f += 32) s += g_gsum[f] * fcW[k * C3 + f];
#pragma unroll
    for (int o = 16; o; o >>= 1) s += __shfl_down_sync(0xffffffffu, s, o);
    if (lane == 0) out[k] = s * (1.f / NN) + fcb[k];
}

extern "C" void kernel_launch(void* const* d_in, const int* in_sizes, int n_in,
                              void* d_out, int out_size) {
    const float* x   = (const float*)d_in[0];
    const int*   ei  = (const int*)d_in[1];          // int32 (jax x64 disabled)
    const float* W1  = (const float*)d_in[2];
    const float* b1  = (const float*)d_in[3];
    const float* W2  = (const float*)d_in[4];
    const float* b2  = (const float*)d_in[5];
    const float* fcW = (const float*)d_in[6];
    const float* fcb = (const float*)d_in[7];
    float* out = (float*)d_out;

    deginit_k<<<NBLK, 256>>>();
    degcnt_k<<<(NE + 255) / 256, 256>>>(ei);
    dinv_k<<<NBLK, 256>>>();

    // CSR build (reused by both layers)
    scanA_k<<<NBLK, 256>>>();
    scanB_k<<<1, 512>>>();
    scanC_k<<<NBLK, 256>>>();
    fill_k<<<(NE + 255) / 256, 256>>>(ei);

    gemm1_k<<<(NN + 63) / 64, 256>>>(x, W1);
    pull1_k<<<(NN * 32 + 255) / 256, 256>>>(b1);    // warp per node
    pull2_k<<<(NN * 32 + 255) / 256, 256>>>();

    gemm2mean_k<<<(NN + 63) / 64, 256>>>(W2, b2);
    fc_k<<<1, 64>>>(fcW, fcb, out);
}

// round 9
// speedup vs baseline: 1.1789x; 1.1789x over previous
#include <cuda_runtime.h>
#include <cuda_fp16.h>
#include <cstdint>

#define NN 100000
#define NE 3200000
#define C1 256
#define C2 64
#define C3 128
#define NBLK ((NN + 255) / 256)   // 391

// Scratch (static device globals — no allocation allowed)
__device__ __half2 g_hs1h[(size_t)NN * C2 / 2];  // dinv * (x @ W1), fp16
__device__ __half2 g_rs1h[(size_t)NN * C2 / 2];  // dinv * relu(dinv*agg1 + b1), fp16
__device__ float   g_a2[(size_t)NN * C2];        // dinv * layer2 aggregate (fp32)
__device__ int     g_deg[NN];
__device__ float   g_dinv[NN];
__device__ float   g_gsum[C3];
// CSR of in-edges
__device__ int   g_off[NN + 1];
__device__ int   g_cur[NN];
__device__ int   g_csrc[NE];
__device__ int   g_bsum[512];
__device__ int   g_bpre[512];

// ---------------- MMA helpers ----------------
__device__ __forceinline__ uint32_t s2u(const void* p) {
    uint32_t a;
    asm("{ .reg .u64 t; cvta.to.shared.u64 t, %1; cvt.u32.u64 %0, t; }" : "=r"(a) : "l"(p));
    return a;
}
#define LDSM4(r0, r1, r2, r3, addr) \
    asm volatile("ldmatrix.sync.aligned.m8n8.x4.shared.b16 {%0,%1,%2,%3}, [%4];" \
                 : "=r"(r0), "=r"(r1), "=r"(r2), "=r"(r3) : "r"(addr))
#define LDSM2T(r0, r1, addr) \
    asm volatile("ldmatrix.sync.aligned.m8n8.x2.trans.shared.b16 {%0,%1}, [%2];" \
                 : "=r"(r0), "=r"(r1) : "r"(addr))
#define MMA16816(d, a, b) \
    asm volatile("mma.sync.aligned.m16n8k16.row.col.f32.f16.f16.f32 " \
                 "{%0,%1,%2,%3}, {%4,%5,%6,%7}, {%8,%9}, {%0,%1,%2,%3};" \
                 : "+f"((d)[0]), "+f"((d)[1]), "+f"((d)[2]), "+f"((d)[3]) \
                 : "r"((a)[0]), "r"((a)[1]), "r"((a)[2]), "r"((a)[3]), \
                   "r"((b)[0]), "r"((b)[1]))
#define SWZ(off) ((off) ^ (((off) >> 3) & 0x70))

// ---------------- degree / norm ----------------
__global__ void deginit_k() {
    int i = blockIdx.x * blockDim.x + threadIdx.x;
    if (i < NN) g_deg[i] = 1;          // self loop
    if (i < C3) g_gsum[i] = 0.f;
}

__global__ void degcnt_k(const int* __restrict__ ei) {
    int e = blockIdx.x * blockDim.x + threadIdx.x;
    if (e < NE) atomicAdd(&g_deg[ei[NE + e]], 1);
}

__global__ void dinv_k() {
    int i = blockIdx.x * blockDim.x + threadIdx.x;
    if (i < NN) g_dinv[i] = rsqrtf((float)g_deg[i]);
}

// ---------------- CSR build: scan of (deg-1), then cursor fill ----------------
__global__ void scanA_k() {      // per-block sums
    __shared__ int sm[256];
    int i = blockIdx.x * 256 + threadIdx.x;
    sm[threadIdx.x] = (i < NN) ? (g_deg[i] - 1) : 0;
    __syncthreads();
    for (int o = 128; o; o >>= 1) {
        if (threadIdx.x < o) sm[threadIdx.x] += sm[threadIdx.x + o];
        __syncthreads();
    }
    if (threadIdx.x == 0) g_bsum[blockIdx.x] = sm[0];
}

__global__ void scanB_k() {      // exclusive scan of block sums (1 block, 512 thr)
    __shared__ int sm[512];
    int t = threadIdx.x;
    int v = (t < NBLK) ? g_bsum[t] : 0;
    sm[t] = v;
    __syncthreads();
    for (int o = 1; o < 512; o <<= 1) {
        int add = (t >= o) ? sm[t - o] : 0;
        __syncthreads();
        sm[t] += add;
        __syncthreads();
    }
    if (t < NBLK) g_bpre[t] = sm[t] - v;
}

__global__ void scanC_k() {      // intra-block exclusive scan + base -> offsets
    __shared__ int sm[256];
    int t = threadIdx.x;
    int i = blockIdx.x * 256 + t;
    int v = (i < NN) ? (g_deg[i] - 1) : 0;
    sm[t] = v;
    __syncthreads();
    for (int o = 1; o < 256; o <<= 1) {
        int add = (t >= o) ? sm[t - o] : 0;
        __syncthreads();
        sm[t] += add;
        __syncthreads();
    }
    if (i < NN) {
        int off = g_bpre[blockIdx.x] + sm[t] - v;
        g_off[i] = off;
        g_cur[i] = off;
    }
    if (i == 0) g_off[NN] = NE;
}

__global__ void fill_k(const int* __restrict__ ei) {
    int e = blockIdx.x * blockDim.x + threadIdx.x;
    if (e >= NE) return;
    int s = ei[e];
    int d = ei[NE + e];
    int pos = atomicAdd(&g_cur[d], 1);
    g_csrc[pos] = s;
}

// -------- GEMM1 via HMMA: hs1 = fp16(dinv * (x @ W1)), fp32 accum --------
// Block tile M=128, N=64(full), K chunks of 64. 8 warps = 4x2 (warp tile 32x32).
__global__ void gemm1_k(const float* __restrict__ x, const float* __restrict__ W1) {
    __shared__ __align__(128) __half As[128 * 64];   // 128 rows x 64 halves (128B/row)
    __shared__ __align__(128) __half Bs[64 * 64];    // 64 k-rows x 64 n-halves
    const int tid = threadIdx.x;
    const int lane = tid & 31, warp = tid >> 5;
    const int wm = warp >> 1, wn = warp & 1;
    const int row0 = blockIdx.x * 128;
    const uint32_t smA = s2u(As), smB = s2u(Bs);

    float acc[2][4][4];
#pragma unroll
    for (int t = 0; t < 2; t++)
#pragma unroll
        for (int nt = 0; nt < 4; nt++)
#pragma unroll
            for (int q = 0; q < 4; q++) acc[t][nt][q] = 0.f;

    for (int kc = 0; kc < C1; kc += 64) {
        // load A chunk: 128 rows x 64 floats -> fp16 swizzled
#pragma unroll
        for (int i = 0; i < 8; i++) {
            int li = tid + i * 256;           // 2048 float4
            int r = li >> 4, c4 = li & 15;
            int grow = row0 + r;
            float4 v = make_float4(0.f, 0.f, 0.f, 0.f);
            if (grow < NN) v = *(const float4*)(x + (size_t)grow * C1 + kc + c4 * 4);
            uint32_t off = (uint32_t)(r * 128 + c4 * 8);   // bytes
            *(half2*)((char*)As + SWZ(off))     = __floats2half2_rn(v.x, v.y);
            *(half2*)((char*)As + SWZ(off + 4)) = __floats2half2_rn(v.z, v.w);
        }
        // load B chunk: 64 k-rows x 64 floats
#pragma unroll
        for (int i = 0; i < 4; i++) {
            int li = tid + i * 256;           // 1024 float4
            int r = li >> 4, c4 = li & 15;
            float4 v = *(const float4*)(W1 + (size_t)(kc + r) * C2 + c4 * 4);
            uint32_t off = (uint32_t)(r * 128 + c4 * 8);
            *(half2*)((char*)Bs + SWZ(off))     = __floats2half2_rn(v.x, v.y);
            *(half2*)((char*)Bs + SWZ(off + 4)) = __floats2half2_rn(v.z, v.w);
        }
        __syncthreads();

#pragma unroll
        for (int kk = 0; kk < 64; kk += 16) {
            uint32_t a[2][4], b[4][2];
#pragma unroll
            for (int t = 0; t < 2; t++) {
                uint32_t off = (uint32_t)((wm * 32 + t * 16 + (lane & 15)) * 128
                                          + (kk + (lane >> 4) * 8) * 2);
                LDSM4(a[t][0], a[t][1], a[t][2], a[t][3], smA + SWZ(off));
            }
#pragma unroll
            for (int nt = 0; nt < 4; nt++) {
                uint32_t off = (uint32_t)((kk + (lane & 15)) * 128
                                          + (wn * 32 + nt * 8) * 2);
                LDSM2T(b[nt][0], b[nt][1], smB + SWZ(off));
            }
#pragma unroll
            for (int t = 0; t < 2; t++)
#pragma unroll
                for (int nt = 0; nt < 4; nt++) MMA16816(acc[t][nt], a[t], b[nt]);
        }
        __syncthreads();
    }

    // epilogue: scale by dinv, write fp16 hs1
#pragma unroll
    for (int t = 0; t < 2; t++) {
        int ra = row0 + wm * 32 + t * 16 + (lane >> 2);
        int rb = ra + 8;
        float dva = (ra < NN) ? g_dinv[ra] : 0.f;
        float dvb = (rb < NN) ? g_dinv[rb] : 0.f;
#pragma unroll
        for (int nt = 0; nt < 4; nt++) {
            int col2 = wn * 16 + nt * 4 + (lane & 3);   // half2 index within row
            if (ra < NN)
                g_hs1h[(size_t)ra * 32 + col2] =
                    __floats2half2_rn(acc[t][nt][0] * dva, acc[t][nt][1] * dva);
            if (rb < NN)
                g_hs1h[(size_t)rb * 32 + col2] =
                    __floats2half2_rn(acc[t][nt][2] * dvb, acc[t][nt][3] * dvb);
        }
    }
}

// ------------- pull layer1: warp per node, fp16 gather, fp32 accumulate -------------
// rs1[d] = fp16( dinv_d * relu(dinv_d * (hs1[d] + sum_in hs1[s]) + b1) )
__global__ void pull1_k(const float* __restrict__ b1) {
    int w = (blockIdx.x * blockDim.x + threadIdx.x) >> 5;
    if (w >= NN) return;
    int lane = threadIdx.x & 31;
    int beg = g_off[w], end = g_off[w + 1];
    float2 acc = __half22float2(g_hs1h[(size_t)w * 32 + lane]);   // self loop
    int i = beg;
    while (i < end) {
        int n = end - i; if (n > 32) n = 32;
        int idx = 0;
        if (lane < n) idx = __ldg(g_csrc + i + lane);
#pragma unroll 4
        for (int j = 0; j < n; j++) {
            int s = __shfl_sync(0xffffffffu, idx, j);
            float2 v = __half22float2(g_hs1h[(size_t)s * 32 + lane]);
            acc.x += v.x; acc.y += v.y;
        }
        i += n;
    }
    float dv = g_dinv[w];
    float2 bb = *((const float2*)b1 + lane);
    acc.x = fmaxf(acc.x * dv + bb.x, 0.f) * dv;
    acc.y = fmaxf(acc.y * dv + bb.y, 0.f) * dv;
    g_rs1h[(size_t)w * 32 + lane] = __floats2half2_rn(acc.x, acc.y);
}

// ------------- pull layer2: a2[d] = dinv_d * (rs1[d] + sum_in rs1[s]) -------------
__global__ void pull2_k() {
    int w = (blockIdx.x * blockDim.x + threadIdx.x) >> 5;
    if (w >= NN) return;
    int lane = threadIdx.x & 31;
    int beg = g_off[w], end = g_off[w + 1];
    float2 acc = __half22float2(g_rs1h[(size_t)w * 32 + lane]);   // self loop
    int i = beg;
    while (i < end) {
        int n = end - i; if (n > 32) n = 32;
        int idx = 0;
        if (lane < n) idx = __ldg(g_csrc + i + lane);
#pragma unroll 4
        for (int j = 0; j < n; j++) {
            int s = __shfl_sync(0xffffffffu, idx, j);
            float2 v = __half22float2(g_rs1h[(size_t)s * 32 + lane]);
            acc.x += v.x; acc.y += v.y;
        }
        i += n;
    }
    float dv = g_dinv[w];
    acc.x *= dv; acc.y *= dv;
    *((float2*)(g_a2 + (size_t)w * C2) + lane) = acc;
}

// --------- GEMM2 + mean fused: gsum += colsum(relu(a2 @ W2 + b2)) ---------
__global__ void gemm2mean_k(const float* __restrict__ W2, const float* __restrict__ b2) {
    __shared__ float xs[64][64];
    __shared__ float ws[64][128];
    __shared__ float rsm[16][132];
    int row0 = blockIdx.x * 64;
    int tid = threadIdx.x;
    int ty = tid >> 4, tx = tid & 15;

#pragma unroll
    for (int i = 0; i < 8; i++) {
        int li = tid + i * 256;            // 32 float4 per row
        int r = li >> 5, c4 = li & 31;
        *(float4*)&ws[r][c4 * 4] = *(const float4*)(W2 + (size_t)r * C3 + c4 * 4);
    }
#pragma unroll
    for (int i = 0; i < 4; i++) {
        int li = tid + i * 256;            // 16 float4 per row
        int r = li >> 4, c4 = li & 15;
        int grow = row0 + r;
        float4 v = make_float4(0.f, 0.f, 0.f, 0.f);
        if (grow < NN) v = *(const float4*)(g_a2 + (size_t)grow * C2 + c4 * 4);
        *(float4*)&xs[r][c4 * 4] = v;
    }
    __syncthreads();

    float acc[4][8];
#pragma unroll
    for (int i = 0; i < 4; i++)
#pragma unroll
        for (int j = 0; j < 8; j++) acc[i][j] = 0.f;

#pragma unroll
    for (int k = 0; k < 64; k++) {
        float a[4], b[8];
#pragma unroll
        for (int i = 0; i < 4; i++) a[i] = xs[ty * 4 + i][k];
#pragma unroll
        for (int j = 0; j < 8; j++) b[j] = ws[k][tx * 8 + j];
#pragma unroll
        for (int i = 0; i < 4; i++)
#pragma unroll
            for (int j = 0; j < 8; j++) acc[i][j] += a[i] * b[j];
    }

    float part[8];
#pragma unroll
    for (int j = 0; j < 8; j++) {
        float bias = b2[tx * 8 + j];
        float s = 0.f;
#pragma unroll
        for (int i = 0; i < 4; i++) {
            int grow = row0 + ty * 4 + i;
            if (grow < NN) s += fmaxf(acc[i][j] + bias, 0.f);
        }
        part[j] = s;
    }
#pragma unroll
    for (int j = 0; j < 8; j++) rsm[ty][tx * 8 + j] = part[j];
    __syncthreads();

    if (tid < C3) {
        float s = 0.f;
#pragma unroll
        for (int r = 0; r < 16; r++) s += rsm[r][tid];
        atomicAdd(&g_gsum[tid], s);
    }
}

// ---------------- final FC: out[k] = (gsum/N) . fcW[k] + fcb[k] ----------------
__global__ void fc_k(const float* __restrict__ fcW, const float* __restrict__ fcb,
                     float* __restrict__ out) {
    int k = threadIdx.x >> 5, lane = threadIdx.x & 31;
    float s = 0.f;
    for (int f = lane; f < C3; f += 32) s += g_gsum[f] * fcW[k * C3 + f];
#pragma unroll
    for (int o = 16; o; o >>= 1) s += __shfl_down_sync(0xffffffffu, s, o);
    if (lane == 0) out[k] = s * (1.f / NN) + fcb[k];
}

extern "C" void kernel_launch(void* const* d_in, const int* in_sizes, int n_in,
                              void* d_out, int out_size) {
    const float* x   = (const float*)d_in[0];
    const int*   ei  = (const int*)d_in[1];          // int32 (jax x64 disabled)
    const float* W1  = (const float*)d_in[2];
    const float* b1  = (const float*)d_in[3];
    const float* W2  = (const float*)d_in[4];
    const float* b2  = (const float*)d_in[5];
    const float* fcW = (const float*)d_in[6];
    const float* fcb = (const float*)d_in[7];
    float* out = (float*)d_out;

    deginit_k<<<NBLK, 256>>>();
    degcnt_k<<<(NE + 255) / 256, 256>>>(ei);
    dinv_k<<<NBLK, 256>>>();

    // CSR build (reused by both layers)
    scanA_k<<<NBLK, 256>>>();
    scanB_k<<<1, 512>>>();
    scanC_k<<<NBLK, 256>>>();
    fill_k<<<(NE + 255) / 256, 256>>>(ei);

    gemm1_k<<<(NN + 127) / 128, 256>>>(x, W1);      // HMMA, 128-row tiles
    pull1_k<<<(NN * 32 + 255) / 256, 256>>>(b1);    // warp per node
    pull2_k<<<(NN * 32 + 255) / 256, 256>>>();

    gemm2mean_k<<<(NN + 63) / 64, 256>>>(W2, b2);
    fc_k<<<1, 64>>>(fcW, fcb, out);
}

// round 10
// speedup vs baseline: 1.4778x; 1.2535x over previous
#include <cuda_runtime.h>
#include <cuda_fp16.h>
#include <cstdint>

#define NN 100000
#define NE 3200000
#define C1 256
#define C2 64
#define C3 128
#define NBLK ((NN + 255) / 256)   // 391

// Scratch (static device globals — no allocation allowed)
__device__ __half2 g_hs1h[(size_t)NN * C2 / 2];  // dinv * (x @ W1), fp16
__device__ __half2 g_rs1h[(size_t)NN * C2 / 2];  // dinv * relu(dinv*agg1 + b1), fp16
__device__ __half2 g_a2h [(size_t)NN * C2 / 2];  // dinv * layer2 aggregate, fp16
__device__ int     g_deg[NN];
__device__ float   g_dinv[NN];
__device__ float   g_gsum[C3];
// CSR of in-edges
__device__ int   g_off[NN + 1];
__device__ int   g_cur[NN];
__device__ int   g_csrc[NE];
__device__ int   g_bsum[512];
__device__ int   g_bpre[512];

// ---------------- MMA helpers ----------------
__device__ __forceinline__ uint32_t s2u(const void* p) {
    uint32_t a;
    asm("{ .reg .u64 t; cvta.to.shared.u64 t, %1; cvt.u32.u64 %0, t; }" : "=r"(a) : "l"(p));
    return a;
}
#define LDSM4(r0, r1, r2, r3, addr) \
    asm volatile("ldmatrix.sync.aligned.m8n8.x4.shared.b16 {%0,%1,%2,%3}, [%4];" \
                 : "=r"(r0), "=r"(r1), "=r"(r2), "=r"(r3) : "r"(addr))
#define LDSM2T(r0, r1, addr) \
    asm volatile("ldmatrix.sync.aligned.m8n8.x2.trans.shared.b16 {%0,%1}, [%2];" \
                 : "=r"(r0), "=r"(r1) : "r"(addr))
#define MMA16816(d, a, b) \
    asm volatile("mma.sync.aligned.m16n8k16.row.col.f32.f16.f16.f32 " \
                 "{%0,%1,%2,%3}, {%4,%5,%6,%7}, {%8,%9}, {%0,%1,%2,%3};" \
                 : "+f"((d)[0]), "+f"((d)[1]), "+f"((d)[2]), "+f"((d)[3]) \
                 : "r"((a)[0]), "r"((a)[1]), "r"((a)[2]), "r"((a)[3]), \
                   "r"((b)[0]), "r"((b)[1]))
#define SWZ(off) ((off) ^ (((off) >> 3) & 0x70))

__device__ __forceinline__ float4 h4tof4(uint2 v) {
    float2 fa = __half22float2(*(__half2*)&v.x);
    float2 fb = __half22float2(*(__half2*)&v.y);
    return make_float4(fa.x, fa.y, fb.x, fb.y);
}

// ---------------- degree / norm ----------------
__global__ void deginit_k() {
    int i = blockIdx.x * blockDim.x + threadIdx.x;
    if (i < NN) g_deg[i] = 1;          // self loop
    if (i < C3) g_gsum[i] = 0.f;
}

__global__ void degcnt_k(const int* __restrict__ ei) {
    int e = blockIdx.x * blockDim.x + threadIdx.x;
    if (e < NE) atomicAdd(&g_deg[ei[NE + e]], 1);
}

__global__ void dinv_k() {
    int i = blockIdx.x * blockDim.x + threadIdx.x;
    if (i < NN) g_dinv[i] = rsqrtf((float)g_deg[i]);
}

// ---------------- CSR build: scan of (deg-1), then cursor fill ----------------
__global__ void scanA_k() {      // per-block sums
    __shared__ int sm[256];
    int i = blockIdx.x * 256 + threadIdx.x;
    sm[threadIdx.x] = (i < NN) ? (g_deg[i] - 1) : 0;
    __syncthreads();
    for (int o = 128; o; o >>= 1) {
        if (threadIdx.x < o) sm[threadIdx.x] += sm[threadIdx.x + o];
        __syncthreads();
    }
    if (threadIdx.x == 0) g_bsum[blockIdx.x] = sm[0];
}

__global__ void scanB_k() {      // exclusive scan of block sums (1 block, 512 thr)
    __shared__ int sm[512];
    int t = threadIdx.x;
    int v = (t < NBLK) ? g_bsum[t] : 0;
    sm[t] = v;
    __syncthreads();
    for (int o = 1; o < 512; o <<= 1) {
        int add = (t >= o) ? sm[t - o] : 0;
        __syncthreads();
        sm[t] += add;
        __syncthreads();
    }
    if (t < NBLK) g_bpre[t] = sm[t] - v;
}

__global__ void scanC_k() {      // intra-block exclusive scan + base -> offsets
    __shared__ int sm[256];
    int t = threadIdx.x;
    int i = blockIdx.x * 256 + t;
    int v = (i < NN) ? (g_deg[i] - 1) : 0;
    sm[t] = v;
    __syncthreads();
    for (int o = 1; o < 256; o <<= 1) {
        int add = (t >= o) ? sm[t - o] : 0;
        __syncthreads();
        sm[t] += add;
        __syncthreads();
    }
    if (i < NN) {
        int off = g_bpre[blockIdx.x] + sm[t] - v;
        g_off[i] = off;
        g_cur[i] = off;
    }
    if (i == 0) g_off[NN] = NE;
}

__global__ void fill_k(const int* __restrict__ ei) {
    int e = blockIdx.x * blockDim.x + threadIdx.x;
    if (e >= NE) return;
    int s = ei[e];
    int d = ei[NE + e];
    int pos = atomicAdd(&g_cur[d], 1);
    g_csrc[pos] = s;
}

// -------- GEMM1 via HMMA: hs1 = fp16(dinv * (x @ W1)), fp32 accum --------
__global__ void gemm1_k(const float* __restrict__ x, const float* __restrict__ W1) {
    __shared__ __align__(128) __half As[128 * 64];
    __shared__ __align__(128) __half Bs[64 * 64];
    const int tid = threadIdx.x;
    const int lane = tid & 31, warp = tid >> 5;
    const int wm = warp >> 1, wn = warp & 1;
    const int row0 = blockIdx.x * 128;
    const uint32_t smA = s2u(As), smB = s2u(Bs);

    float acc[2][4][4];
#pragma unroll
    for (int t = 0; t < 2; t++)
#pragma unroll
        for (int nt = 0; nt < 4; nt++)
#pragma unroll
            for (int q = 0; q < 4; q++) acc[t][nt][q] = 0.f;

    for (int kc = 0; kc < C1; kc += 64) {
#pragma unroll
        for (int i = 0; i < 8; i++) {
            int li = tid + i * 256;
            int r = li >> 4, c4 = li & 15;
            int grow = row0 + r;
            float4 v = make_float4(0.f, 0.f, 0.f, 0.f);
            if (grow < NN) v = *(const float4*)(x + (size_t)grow * C1 + kc + c4 * 4);
            uint32_t off = (uint32_t)(r * 128 + c4 * 8);
            *(half2*)((char*)As + SWZ(off))     = __floats2half2_rn(v.x, v.y);
            *(half2*)((char*)As + SWZ(off + 4)) = __floats2half2_rn(v.z, v.w);
        }
#pragma unroll
        for (int i = 0; i < 4; i++) {
            int li = tid + i * 256;
            int r = li >> 4, c4 = li & 15;
            float4 v = *(const float4*)(W1 + (size_t)(kc + r) * C2 + c4 * 4);
            uint32_t off = (uint32_t)(r * 128 + c4 * 8);
            *(half2*)((char*)Bs + SWZ(off))     = __floats2half2_rn(v.x, v.y);
            *(half2*)((char*)Bs + SWZ(off + 4)) = __floats2half2_rn(v.z, v.w);
        }
        __syncthreads();

#pragma unroll
        for (int kk = 0; kk < 64; kk += 16) {
            uint32_t a[2][4], b[4][2];
#pragma unroll
            for (int t = 0; t < 2; t++) {
                uint32_t off = (uint32_t)((wm * 32 + t * 16 + (lane & 15)) * 128
                                          + (kk + (lane >> 4) * 8) * 2);
                LDSM4(a[t][0], a[t][1], a[t][2], a[t][3], smA + SWZ(off));
            }
#pragma unroll
            for (int nt = 0; nt < 4; nt++) {
                uint32_t off = (uint32_t)((kk + (lane & 15)) * 128
                                          + (wn * 32 + nt * 8) * 2);
                LDSM2T(b[nt][0], b[nt][1], smB + SWZ(off));
            }
#pragma unroll
            for (int t = 0; t < 2; t++)
#pragma unroll
                for (int nt = 0; nt < 4; nt++) MMA16816(acc[t][nt], a[t], b[nt]);
        }
        __syncthreads();
    }

#pragma unroll
    for (int t = 0; t < 2; t++) {
        int ra = row0 + wm * 32 + t * 16 + (lane >> 2);
        int rb = ra + 8;
        float dva = (ra < NN) ? g_dinv[ra] : 0.f;
        float dvb = (rb < NN) ? g_dinv[rb] : 0.f;
#pragma unroll
        for (int nt = 0; nt < 4; nt++) {
            int col2 = wn * 16 + nt * 4 + (lane & 3);
            if (ra < NN)
                g_hs1h[(size_t)ra * 32 + col2] =
                    __floats2half2_rn(acc[t][nt][0] * dva, acc[t][nt][1] * dva);
            if (rb < NN)
                g_hs1h[(size_t)rb * 32 + col2] =
                    __floats2half2_rn(acc[t][nt][2] * dvb, acc[t][nt][3] * dvb);
        }
    }
}

// ------ pull layer1: warp per node, 2 edges in flight (16 lanes x 8B each) ------
// rs1[d] = fp16( dinv_d * relu(dinv_d * (hs1[d] + sum_in hs1[s]) + b1) )
__global__ void pull1_k(const float* __restrict__ b1) {
    int w = (blockIdx.x * blockDim.x + threadIdx.x) >> 5;
    if (w >= NN) return;
    int lane = threadIdx.x & 31;
    int half = lane >> 4, hl = lane & 15;
    int beg = g_off[w], end = g_off[w + 1];
    float4 acc = make_float4(0.f, 0.f, 0.f, 0.f);
    if (half == 0)
        acc = h4tof4(((const uint2*)(g_hs1h + (size_t)w * 32))[hl]);   // self loop
    int i = beg;
    while (i < end) {
        int n = end - i; if (n > 32) n = 32;
        int idx = 0;
        if (lane < n) idx = __ldg(g_csrc + i + lane);
#pragma unroll 4
        for (int j = 0; j < n; j += 2) {
            int e = j + half;
            int s = __shfl_sync(0xffffffffu, idx, e & 31);
            if (e < n) {
                float4 f = h4tof4(((const uint2*)(g_hs1h + (size_t)s * 32))[hl]);
                acc.x += f.x; acc.y += f.y; acc.z += f.z; acc.w += f.w;
            }
        }
        i += n;
    }
    acc.x += __shfl_xor_sync(0xffffffffu, acc.x, 16);
    acc.y += __shfl_xor_sync(0xffffffffu, acc.y, 16);
    acc.z += __shfl_xor_sync(0xffffffffu, acc.z, 16);
    acc.w += __shfl_xor_sync(0xffffffffu, acc.w, 16);
    if (half == 0) {
        float dv = g_dinv[w];
        float4 bb = ((const float4*)b1)[hl];
        acc.x = fmaxf(acc.x * dv + bb.x, 0.f) * dv;
        acc.y = fmaxf(acc.y * dv + bb.y, 0.f) * dv;
        acc.z = fmaxf(acc.z * dv + bb.z, 0.f) * dv;
        acc.w = fmaxf(acc.w * dv + bb.w, 0.f) * dv;
        uint2 o;
        *(__half2*)&o.x = __floats2half2_rn(acc.x, acc.y);
        *(__half2*)&o.y = __floats2half2_rn(acc.z, acc.w);
        ((uint2*)(g_rs1h + (size_t)w * 32))[hl] = o;
    }
}

// ------ pull layer2: a2[d] = fp16( dinv_d * (rs1[d] + sum_in rs1[s]) ) ------
__global__ void pull2_k() {
    int w = (blockIdx.x * blockDim.x + threadIdx.x) >> 5;
    if (w >= NN) return;
    int lane = threadIdx.x & 31;
    int half = lane >> 4, hl = lane & 15;
    int beg = g_off[w], end = g_off[w + 1];
    float4 acc = make_float4(0.f, 0.f, 0.f, 0.f);
    if (half == 0)
        acc = h4tof4(((const uint2*)(g_rs1h + (size_t)w * 32))[hl]);   // self loop
    int i = beg;
    while (i < end) {
        int n = end - i; if (n > 32) n = 32;
        int idx = 0;
        if (lane < n) idx = __ldg(g_csrc + i + lane);
#pragma unroll 4
        for (int j = 0; j < n; j += 2) {
            int e = j + half;
            int s = __shfl_sync(0xffffffffu, idx, e & 31);
            if (e < n) {
                float4 f = h4tof4(((const uint2*)(g_rs1h + (size_t)s * 32))[hl]);
                acc.x += f.x; acc.y += f.y; acc.z += f.z; acc.w += f.w;
            }
        }
        i += n;
    }
    acc.x += __shfl_xor_sync(0xffffffffu, acc.x, 16);
    acc.y += __shfl_xor_sync(0xffffffffu, acc.y, 16);
    acc.z += __shfl_xor_sync(0xffffffffu, acc.z, 16);
    acc.w += __shfl_xor_sync(0xffffffffu, acc.w, 16);
    if (half == 0) {
        float dv = g_dinv[w];
        uint2 o;
        *(__half2*)&o.x = __floats2half2_rn(acc.x * dv, acc.y * dv);
        *(__half2*)&o.y = __floats2half2_rn(acc.z * dv, acc.w * dv);
        ((uint2*)(g_a2h + (size_t)w * 32))[hl] = o;
    }
}

// --- GEMM2 + mean fused via HMMA: gsum += colsum(relu(a2 @ W2 + b2)) ---
// Block tile M=128, N=128(full), K=64. 8 warps = 4x2 (warp tile 32x64).
__global__ void gemm2mean_k(const float* __restrict__ W2, const float* __restrict__ b2) {
    __shared__ __align__(128) __half As[128 * 64];      // a2 tile (128B rows)
    __shared__ __align__(128) __half Bs[2][64 * 64];    // W2 as two 64x64 n-tiles
    __shared__ float colsum[C3];
    const int tid = threadIdx.x;
    const int lane = tid & 31, warp = tid >> 5;
    const int wm = warp >> 1, wn = warp & 1;
    const int row0 = blockIdx.x * 128;
    const uint32_t smA = s2u(As), smB = s2u(Bs);

    if (tid < C3) colsum[tid] = 0.f;

    // load W2 (64x128 fp32) -> fp16 swizzled, split into n-tiles
#pragma unroll
    for (int i = 0; i < 8; i++) {
        int li = tid + i * 256;           // 2048 float4
        int r = li >> 5, c4 = li & 31;
        float4 v = *(const float4*)(W2 + (size_t)r * C3 + c4 * 4);
        int ncol = c4 * 4;
        int tile = ncol >> 6;
        uint32_t off = (uint32_t)(r * 128 + (ncol & 63) * 2);
        char* base = (char*)Bs + tile * 8192;
        *(half2*)(base + SWZ(off))     = __floats2half2_rn(v.x, v.y);
        *(half2*)(base + SWZ(off + 4)) = __floats2half2_rn(v.z, v.w);
    }
    // load a2 tile (fp16 raw copy, swizzled): 128 rows x 128B = 1024 uint4
#pragma unroll
    for (int i = 0; i < 4; i++) {
        int li = tid + i * 256;
        int r = li >> 3, c = li & 7;
        int grow = row0 + r;
        uint4 v = make_uint4(0u, 0u, 0u, 0u);
        if (grow < NN) v = ((const uint4*)(g_a2h + (size_t)grow * 32))[c];
        *(uint4*)((char*)As + SWZ((uint32_t)(r * 128 + c * 16))) = v;
    }
    __syncthreads();

    float acc[2][8][4];
#pragma unroll
    for (int t = 0; t < 2; t++)
#pragma unroll
        for (int nt = 0; nt < 8; nt++)
#pragma unroll
            for (int q = 0; q < 4; q++) acc[t][nt][q] = 0.f;

#pragma unroll
    for (int kk = 0; kk < 64; kk += 16) {
        uint32_t a[2][4], b[8][2];
#pragma unroll
        for (int t = 0; t < 2; t++) {
            uint32_t off = (uint32_t)((wm * 32 + t * 16 + (lane & 15)) * 128
                                      + (kk + (lane >> 4) * 8) * 2);
            LDSM4(a[t][0], a[t][1], a[t][2], a[t][3], smA + SWZ(off));
        }
#pragma unroll
        for (int nt = 0; nt < 8; nt++) {
            uint32_t off = (uint32_t)((kk + (lane & 15)) * 128 + (nt * 8) * 2);
            LDSM2T(b[nt][0], b[nt][1], smB + wn * 8192 + SWZ(off));
        }
#pragma unroll
        for (int t = 0; t < 2; t++)
#pragma unroll
            for (int nt = 0; nt < 8; nt++) MMA16816(acc[t][nt], a[t], b[nt]);
    }

    // epilogue: bias+relu per element, sum over valid rows, reduce, accumulate
#pragma unroll
    for (int nt = 0; nt < 8; nt++) {
        int c0 = wn * 64 + nt * 8 + (lane & 3) * 2;
        float bias0 = b2[c0], bias1 = b2[c0 + 1];
        float s0 = 0.f, s1 = 0.f;
#pragma unroll
        for (int t = 0; t < 2; t++) {
            int ra = row0 + wm * 32 + t * 16 + (lane >> 2);
            int rb = ra + 8;
            if (ra < NN) { s0 += fmaxf(acc[t][nt][0] + bias0, 0.f);
                           s1 += fmaxf(acc[t][nt][1] + bias1, 0.f); }
            if (rb < NN) { s0 += fmaxf(acc[t][nt][2] + bias0, 0.f);
                           s1 += fmaxf(acc[t][nt][3] + bias1, 0.f); }
        }
        s0 += __shfl_xor_sync(0xffffffffu, s0, 4);
        s0 += __shfl_xor_sync(0xffffffffu, s0, 8);
        s0 += __shfl_xor_sync(0xffffffffu, s0, 16);
        s1 += __shfl_xor_sync(0xffffffffu, s1, 4);
        s1 += __shfl_xor_sync(0xffffffffu, s1, 8);
        s1 += __shfl_xor_sync(0xffffffffu, s1, 16);
        if (lane < 4) {
            atomicAdd(&colsum[c0], s0);
            atomicAdd(&colsum[c0 + 1], s1);
        }
    }
    __syncthreads();
    if (tid < C3) atomicAdd(&g_gsum[tid], colsum[tid]);
}

// ---------------- final FC: out[k] = (gsum/N) . fcW[k] + fcb[k] ----------------
__global__ void fc_k(const float* __restrict__ fcW, const float* __restrict__ fcb,
                     float* __restrict__ out) {
    int k = threadIdx.x >> 5, lane = threadIdx.x & 31;
    float s = 0.f;
    for (int f = lane; f < C3; f += 32) s += g_gsum[f] * fcW[k * C3 + f];
#pragma unroll
    for (int o = 16; o; o >>= 1) s += __shfl_down_sync(0xffffffffu, s, o);
    if (lane == 0) out[k] = s * (1.f / NN) + fcb[k];
}

extern "C" void kernel_launch(void* const* d_in, const int* in_sizes, int n_in,
                              void* d_out, int out_size) {
    const float* x   = (const float*)d_in[0];
    const int*   ei  = (const int*)d_in[1];          // int32 (jax x64 disabled)
    const float* W1  = (const float*)d_in[2];
    const float* b1  = (const float*)d_in[3];
    const float* W2  = (const float*)d_in[4];
    const float* b2  = (const float*)d_in[5];
    const float* fcW = (const float*)d_in[6];
    const float* fcb = (const float*)d_in[7];
    float* out = (float*)d_out;

    deginit_k<<<NBLK, 256>>>();
    degcnt_k<<<(NE + 255) / 256, 256>>>(ei);
    dinv_k<<<NBLK, 256>>>();

    // CSR build (reused by both layers)
    scanA_k<<<NBLK, 256>>>();
    scanB_k<<<1, 512>>>();
    scanC_k<<<NBLK, 256>>>();
    fill_k<<<(NE + 255) / 256, 256>>>(ei);

    gemm1_k<<<(NN + 127) / 128, 256>>>(x, W1);      // HMMA, 128-row tiles
    pull1_k<<<(NN * 32 + 255) / 256, 256>>>(b1);    // warp per node, paired edges
    pull2_k<<<(NN * 32 + 255) / 256, 256>>>();

    gemm2mean_k<<<(NN + 127) / 128, 256>>>(W2, b2); // HMMA + fused mean
    fc_k<<<1, 64>>>(fcW, fcb, out);
}

// round 11
// speedup vs baseline: 1.5551x; 1.0523x over previous
#include <cuda_runtime.h>
#include <cuda_fp16.h>
#include <cstdint>

#define NN 100000
#define NE 3200000
#define C1 256
#define C2 64
#define C3 128
#define NBLK ((NN + 255) / 256)   // 391

// Scratch (static device globals — no allocation allowed)
__device__ __half2 g_hs1h[(size_t)NN * C2 / 2];  // dinv * (x @ W1), fp16
__device__ __half2 g_rs1h[(size_t)NN * C2 / 2];  // dinv * relu(dinv*agg1 + b1), fp16
__device__ __half2 g_a2h [(size_t)NN * C2 / 2];  // dinv * layer2 aggregate, fp16
__device__ int     g_deg[NN];
__device__ float   g_dinv[NN];
__device__ float   g_gsum[C3];
// CSR of in-edges
__device__ int   g_off[NN + 1];
__device__ int   g_cur[NN];
__device__ int   g_csrc[NE];
__device__ int   g_bsum[512];
__device__ int   g_bpre[512];

// ---------------- MMA helpers ----------------
__device__ __forceinline__ uint32_t s2u(const void* p) {
    uint32_t a;
    asm("{ .reg .u64 t; cvta.to.shared.u64 t, %1; cvt.u32.u64 %0, t; }" : "=r"(a) : "l"(p));
    return a;
}
#define LDSM4(r0, r1, r2, r3, addr) \
    asm volatile("ldmatrix.sync.aligned.m8n8.x4.shared.b16 {%0,%1,%2,%3}, [%4];" \
                 : "=r"(r0), "=r"(r1), "=r"(r2), "=r"(r3) : "r"(addr))
#define LDSM2T(r0, r1, addr) \
    asm volatile("ldmatrix.sync.aligned.m8n8.x2.trans.shared.b16 {%0,%1}, [%2];" \
                 : "=r"(r0), "=r"(r1) : "r"(addr))
#define MMA16816(d, a, b) \
    asm volatile("mma.sync.aligned.m16n8k16.row.col.f32.f16.f16.f32 " \
                 "{%0,%1,%2,%3}, {%4,%5,%6,%7}, {%8,%9}, {%0,%1,%2,%3};" \
                 : "+f"((d)[0]), "+f"((d)[1]), "+f"((d)[2]), "+f"((d)[3]) \
                 : "r"((a)[0]), "r"((a)[1]), "r"((a)[2]), "r"((a)[3]), \
                   "r"((b)[0]), "r"((b)[1]))
#define SWZ(off) ((off) ^ (((off) >> 3) & 0x70))

// accumulate 8 halves (uint4) into 8 fp32 lanes
__device__ __forceinline__ void acc8(float* a, uint4 v) {
    float2 f0 = __half22float2(*(__half2*)&v.x);
    float2 f1 = __half22float2(*(__half2*)&v.y);
    float2 f2 = __half22float2(*(__half2*)&v.z);
    float2 f3 = __half22float2(*(__half2*)&v.w);
    a[0] += f0.x; a[1] += f0.y; a[2] += f1.x; a[3] += f1.y;
    a[4] += f2.x; a[5] += f2.y; a[6] += f3.x; a[7] += f3.y;
}

// ---------------- degree / norm ----------------
__global__ void deginit_k() {
    int i = blockIdx.x * blockDim.x + threadIdx.x;
    if (i < NN) g_deg[i] = 1;          // self loop
    if (i < C3) g_gsum[i] = 0.f;
}

__global__ void degcnt_k(const int* __restrict__ ei) {
    int e2 = blockIdx.x * blockDim.x + threadIdx.x;
    if (e2 >= NE / 2) return;
    int2 d = *(const int2*)(ei + NE + e2 * 2);
    atomicAdd(&g_deg[d.x], 1);
    atomicAdd(&g_deg[d.y], 1);
}

// ---------------- CSR build: scan of (deg-1), then cursor fill ----------------
__global__ void scanA_k() {      // per-block sums + dinv
    __shared__ int sm[256];
    int i = blockIdx.x * 256 + threadIdx.x;
    int dg = (i < NN) ? g_deg[i] : 1;
    if (i < NN) g_dinv[i] = rsqrtf((float)dg);
    sm[threadIdx.x] = (i < NN) ? (dg - 1) : 0;
    __syncthreads();
    for (int o = 128; o; o >>= 1) {
        if (threadIdx.x < o) sm[threadIdx.x] += sm[threadIdx.x + o];
        __syncthreads();
    }
    if (threadIdx.x == 0) g_bsum[blockIdx.x] = sm[0];
}

__global__ void scanB_k() {      // exclusive scan of block sums (1 block, 512 thr)
    __shared__ int sm[512];
    int t = threadIdx.x;
    int v = (t < NBLK) ? g_bsum[t] : 0;
    sm[t] = v;
    __syncthreads();
    for (int o = 1; o < 512; o <<= 1) {
        int add = (t >= o) ? sm[t - o] : 0;
        __syncthreads();
        sm[t] += add;
        __syncthreads();
    }
    if (t < NBLK) g_bpre[t] = sm[t] - v;
}

__global__ void scanC_k() {      // intra-block exclusive scan + base -> offsets
    __shared__ int sm[256];
    int t = threadIdx.x;
    int i = blockIdx.x * 256 + t;
    int v = (i < NN) ? (g_deg[i] - 1) : 0;
    sm[t] = v;
    __syncthreads();
    for (int o = 1; o < 256; o <<= 1) {
        int add = (t >= o) ? sm[t - o] : 0;
        __syncthreads();
        sm[t] += add;
        __syncthreads();
    }
    if (i < NN) {
        int off = g_bpre[blockIdx.x] + sm[t] - v;
        g_off[i] = off;
        g_cur[i] = off;
    }
    if (i == 0) g_off[NN] = NE;
}

__global__ void fill_k(const int* __restrict__ ei) {
    int e2 = blockIdx.x * blockDim.x + threadIdx.x;
    if (e2 >= NE / 2) return;
    int2 s = *(const int2*)(ei + e2 * 2);
    int2 d = *(const int2*)(ei + NE + e2 * 2);
    int p0 = atomicAdd(&g_cur[d.x], 1);
    g_csrc[p0] = s.x;
    int p1 = atomicAdd(&g_cur[d.y], 1);
    g_csrc[p1] = s.y;
}

// -------- GEMM1 via HMMA: hs1 = fp16(dinv * (x @ W1)), fp32 accum --------
__global__ void gemm1_k(const float* __restrict__ x, const float* __restrict__ W1) {
    __shared__ __align__(128) __half As[128 * 64];
    __shared__ __align__(128) __half Bs[64 * 64];
    const int tid = threadIdx.x;
    const int lane = tid & 31, warp = tid >> 5;
    const int wm = warp >> 1, wn = warp & 1;
    const int row0 = blockIdx.x * 128;
    const uint32_t smA = s2u(As), smB = s2u(Bs);

    float acc[2][4][4];
#pragma unroll
    for (int t = 0; t < 2; t++)
#pragma unroll
        for (int nt = 0; nt < 4; nt++)
#pragma unroll
            for (int q = 0; q < 4; q++) acc[t][nt][q] = 0.f;

    for (int kc = 0; kc < C1; kc += 64) {
#pragma unroll
        for (int i = 0; i < 8; i++) {
            int li = tid + i * 256;
            int r = li >> 4, c4 = li & 15;
            int grow = row0 + r;
            float4 v = make_float4(0.f, 0.f, 0.f, 0.f);
            if (grow < NN) v = *(const float4*)(x + (size_t)grow * C1 + kc + c4 * 4);
            uint32_t off = (uint32_t)(r * 128 + c4 * 8);
            *(half2*)((char*)As + SWZ(off))     = __floats2half2_rn(v.x, v.y);
            *(half2*)((char*)As + SWZ(off + 4)) = __floats2half2_rn(v.z, v.w);
        }
#pragma unroll
        for (int i = 0; i < 4; i++) {
            int li = tid + i * 256;
            int r = li >> 4, c4 = li & 15;
            float4 v = *(const float4*)(W1 + (size_t)(kc + r) * C2 + c4 * 4);
            uint32_t off = (uint32_t)(r * 128 + c4 * 8);
            *(half2*)((char*)Bs + SWZ(off))     = __floats2half2_rn(v.x, v.y);
            *(half2*)((char*)Bs + SWZ(off + 4)) = __floats2half2_rn(v.z, v.w);
        }
        __syncthreads();

#pragma unroll
        for (int kk = 0; kk < 64; kk += 16) {
            uint32_t a[2][4], b[4][2];
#pragma unroll
            for (int t = 0; t < 2; t++) {
                uint32_t off = (uint32_t)((wm * 32 + t * 16 + (lane & 15)) * 128
                                          + (kk + (lane >> 4) * 8) * 2);
                LDSM4(a[t][0], a[t][1], a[t][2], a[t][3], smA + SWZ(off));
            }
#pragma unroll
            for (int nt = 0; nt < 4; nt++) {
                uint32_t off = (uint32_t)((kk + (lane & 15)) * 128
                                          + (wn * 32 + nt * 8) * 2);
                LDSM2T(b[nt][0], b[nt][1], smB + SWZ(off));
            }
#pragma unroll
            for (int t = 0; t < 2; t++)
#pragma unroll
                for (int nt = 0; nt < 4; nt++) MMA16816(acc[t][nt], a[t], b[nt]);
        }
        __syncthreads();
    }

#pragma unroll
    for (int t = 0; t < 2; t++) {
        int ra = row0 + wm * 32 + t * 16 + (lane >> 2);
        int rb = ra + 8;
        float dva = (ra < NN) ? g_dinv[ra] : 0.f;
        float dvb = (rb < NN) ? g_dinv[rb] : 0.f;
#pragma unroll
        for (int nt = 0; nt < 4; nt++) {
            int col2 = wn * 16 + nt * 4 + (lane & 3);
            if (ra < NN)
                g_hs1h[(size_t)ra * 32 + col2] =
                    __floats2half2_rn(acc[t][nt][0] * dva, acc[t][nt][1] * dva);
            if (rb < NN)
                g_hs1h[(size_t)rb * 32 + col2] =
                    __floats2half2_rn(acc[t][nt][2] * dvb, acc[t][nt][3] * dvb);
        }
    }
}

// ---- pull layer1: warp per node, 4 edges in flight (8 lanes x uint4 each) ----
// rs1[d] = fp16( dinv_d * relu(dinv_d * (hs1[d] + sum_in hs1[s]) + b1) )
__global__ void pull1_k(const float* __restrict__ b1) {
    int w = (blockIdx.x * blockDim.x + threadIdx.x) >> 5;
    if (w >= NN) return;
    int lane = threadIdx.x & 31;
    int q = lane >> 3, ql = lane & 7;
    int beg = g_off[w], end = g_off[w + 1];
    float a[8] = {0.f, 0.f, 0.f, 0.f, 0.f, 0.f, 0.f, 0.f};
    if (q == 0)
        acc8(a, ((const uint4*)(g_hs1h + (size_t)w * 32))[ql]);   // self loop
    int i = beg;
    while (i < end) {
        int n = end - i; if (n > 32) n = 32;
        int idx = 0;
        if (lane < n) idx = __ldg(g_csrc + i + lane);
#pragma unroll 2
        for (int j = 0; j < n; j += 4) {
            int e = j + q;
            int s = __shfl_sync(0xffffffffu, idx, e & 31);
            if (e < n)
                acc8(a, ((const uint4*)(g_hs1h + (size_t)s * 32))[ql]);
        }
        i += n;
    }
#pragma unroll
    for (int t = 0; t < 8; t++) {
        a[t] += __shfl_xor_sync(0xffffffffu, a[t], 8);
        a[t] += __shfl_xor_sync(0xffffffffu, a[t], 16);
    }
    if (q == 0) {
        float dv = g_dinv[w];
        float4 b0 = ((const float4*)b1)[ql * 2];
        float4 b1v = ((const float4*)b1)[ql * 2 + 1];
        float r0 = fmaxf(a[0] * dv + b0.x, 0.f) * dv;
        float r1 = fmaxf(a[1] * dv + b0.y, 0.f) * dv;
        float r2 = fmaxf(a[2] * dv + b0.z, 0.f) * dv;
        float r3 = fmaxf(a[3] * dv + b0.w, 0.f) * dv;
        float r4 = fmaxf(a[4] * dv + b1v.x, 0.f) * dv;
        float r5 = fmaxf(a[5] * dv + b1v.y, 0.f) * dv;
        float r6 = fmaxf(a[6] * dv + b1v.z, 0.f) * dv;
        float r7 = fmaxf(a[7] * dv + b1v.w, 0.f) * dv;
        uint4 o;
        *(__half2*)&o.x = __floats2half2_rn(r0, r1);
        *(__half2*)&o.y = __floats2half2_rn(r2, r3);
        *(__half2*)&o.z = __floats2half2_rn(r4, r5);
        *(__half2*)&o.w = __floats2half2_rn(r6, r7);
        ((uint4*)(g_rs1h + (size_t)w * 32))[ql] = o;
    }
}

// ---- pull layer2: a2[d] = fp16( dinv_d * (rs1[d] + sum_in rs1[s]) ) ----
__global__ void pull2_k() {
    int w = (blockIdx.x * blockDim.x + threadIdx.x) >> 5;
    if (w >= NN) return;
    int lane = threadIdx.x & 31;
    int q = lane >> 3, ql = lane & 7;
    int beg = g_off[w], end = g_off[w + 1];
    float a[8] = {0.f, 0.f, 0.f, 0.f, 0.f, 0.f, 0.f, 0.f};
    if (q == 0)
        acc8(a, ((const uint4*)(g_rs1h + (size_t)w * 32))[ql]);   // self loop
    int i = beg;
    while (i < end) {
        int n = end - i; if (n > 32) n = 32;
        int idx = 0;
        if (lane < n) idx = __ldg(g_csrc + i + lane);
#pragma unroll 2
        for (int j = 0; j < n; j += 4) {
            int e = j + q;
            int s = __shfl_sync(0xffffffffu, idx, e & 31);
            if (e < n)
                acc8(a, ((const uint4*)(g_rs1h + (size_t)s * 32))[ql]);
        }
        i += n;
    }
#pragma unroll
    for (int t = 0; t < 8; t++) {
        a[t] += __shfl_xor_sync(0xffffffffu, a[t], 8);
        a[t] += __shfl_xor_sync(0xffffffffu, a[t], 16);
    }
    if (q == 0) {
        float dv = g_dinv[w];
        uint4 o;
        *(__half2*)&o.x = __floats2half2_rn(a[0] * dv, a[1] * dv);
        *(__half2*)&o.y = __floats2half2_rn(a[2] * dv, a[3] * dv);
        *(__half2*)&o.z = __floats2half2_rn(a[4] * dv, a[5] * dv);
        *(__half2*)&o.w = __floats2half2_rn(a[6] * dv, a[7] * dv);
        ((uint4*)(g_a2h + (size_t)w * 32))[ql] = o;
    }
}

// --- GEMM2 + mean fused via HMMA: gsum += colsum(relu(a2 @ W2 + b2)) ---
__global__ void gemm2mean_k(const float* __restrict__ W2, const float* __restrict__ b2) {
    __shared__ __align__(128) __half As[128 * 64];      // a2 tile (128B rows)
    __shared__ __align__(128) __half Bs[2][64 * 64];    // W2 as two 64x64 n-tiles
    __shared__ float colsum[C3];
    const int tid = threadIdx.x;
    const int lane = tid & 31, warp = tid >> 5;
    const int wm = warp >> 1, wn = warp & 1;
    const int row0 = blockIdx.x * 128;
    const uint32_t smA = s2u(As), smB = s2u(Bs);

    if (tid < C3) colsum[tid] = 0.f;

#pragma unroll
    for (int i = 0; i < 8; i++) {
        int li = tid + i * 256;           // 2048 float4
        int r = li >> 5, c4 = li & 31;
        float4 v = *(const float4*)(W2 + (size_t)r * C3 + c4 * 4);
        int ncol = c4 * 4;
        int tile = ncol >> 6;
        uint32_t off = (uint32_t)(r * 128 + (ncol & 63) * 2);
        char* base = (char*)Bs + tile * 8192;
        *(half2*)(base + SWZ(off))     = __floats2half2_rn(v.x, v.y);
        *(half2*)(base + SWZ(off + 4)) = __floats2half2_rn(v.z, v.w);
    }
#pragma unroll
    for (int i = 0; i < 4; i++) {
        int li = tid + i * 256;
        int r = li >> 3, c = li & 7;
        int grow = row0 + r;
        uint4 v = make_uint4(0u, 0u, 0u, 0u);
        if (grow < NN) v = ((const uint4*)(g_a2h + (size_t)grow * 32))[c];
        *(uint4*)((char*)As + SWZ((uint32_t)(r * 128 + c * 16))) = v;
    }
    __syncthreads();

    float acc[2][8][4];
#pragma unroll
    for (int t = 0; t < 2; t++)
#pragma unroll
        for (int nt = 0; nt < 8; nt++)
#pragma unroll
            for (int q = 0; q < 4; q++) acc[t][nt][q] = 0.f;

#pragma unroll
    for (int kk = 0; kk < 64; kk += 16) {
        uint32_t a[2][4], b[8][2];
#pragma unroll
        for (int t = 0; t < 2; t++) {
            uint32_t off = (uint32_t)((wm * 32 + t * 16 + (lane & 15)) * 128
                                      + (kk + (lane >> 4) * 8) * 2);
            LDSM4(a[t][0], a[t][1], a[t][2], a[t][3], smA + SWZ(off));
        }
#pragma unroll
        for (int nt = 0; nt < 8; nt++) {
            uint32_t off = (uint32_t)((kk + (lane & 15)) * 128 + (nt * 8) * 2);
            LDSM2T(b[nt][0], b[nt][1], smB + wn * 8192 + SWZ(off));
        }
#pragma unroll
        for (int t = 0; t < 2; t++)
#pragma unroll
            for (int nt = 0; nt < 8; nt++) MMA16816(acc[t][nt], a[t], b[nt]);
    }

#pragma unroll
    for (int nt = 0; nt < 8; nt++) {
        int c0 = wn * 64 + nt * 8 + (lane & 3) * 2;
        float bias0 = b2[c0], bias1 = b2[c0 + 1];
        float s0 = 0.f, s1 = 0.f;
#pragma unroll
        for (int t = 0; t < 2; t++) {
            int ra = row0 + wm * 32 + t * 16 + (lane >> 2);
            int rb = ra + 8;
            if (ra < NN) { s0 += fmaxf(acc[t][nt][0] + bias0, 0.f);
                           s1 += fmaxf(acc[t][nt][1] + bias1, 0.f); }
            if (rb < NN) { s0 += fmaxf(acc[t][nt][2] + bias0, 0.f);
                           s1 += fmaxf(acc[t][nt][3] + bias1, 0.f); }
        }
        s0 += __shfl_xor_sync(0xffffffffu, s0, 4);
        s0 += __shfl_xor_sync(0xffffffffu, s0, 8);
        s0 += __shfl_xor_sync(0xffffffffu, s0, 16);
        s1 += __shfl_xor_sync(0xffffffffu, s1, 4);
        s1 += __shfl_xor_sync(0xffffffffu, s1, 8);
        s1 += __shfl_xor_sync(0xffffffffu, s1, 16);
        if (lane < 4) {
            atomicAdd(&colsum[c0], s0);
            atomicAdd(&colsum[c0 + 1], s1);
        }
    }
    __syncthreads();
    if (tid < C3) atomicAdd(&g_gsum[tid], colsum[tid]);
}

// ---------------- final FC: out[k] = (gsum/N) . fcW[k] + fcb[k] ----------------
__global__ void fc_k(const float* __restrict__ fcW, const float* __restrict__ fcb,
                     float* __restrict__ out) {
    int k = threadIdx.x >> 5, lane = threadIdx.x & 31;
    float s = 0.f;
    for (int f = lane; f < C3; f += 32) s += g_gsum[f] * fcW[k * C3 + f];
#pragma unroll
    for (int o = 16; o; o >>= 1) s += __shfl_down_sync(0xffffffffu, s, o);
    if (lane == 0) out[k] = s * (1.f / NN) + fcb[k];
}

extern "C" void kernel_launch(void* const* d_in, const int* in_sizes, int n_in,
                              void* d_out, int out_size) {
    const float* x   = (const float*)d_in[0];
    const int*   ei  = (const int*)d_in[1];          // int32 (jax x64 disabled)
    const float* W1  = (const float*)d_in[2];
    const float* b1  = (const float*)d_in[3];
    const float* W2  = (const float*)d_in[4];
    const float* b2  = (const float*)d_in[5];
    const float* fcW = (const float*)d_in[6];
    const float* fcb = (const float*)d_in[7];
    float* out = (float*)d_out;

    deginit_k<<<NBLK, 256>>>();
    degcnt_k<<<(NE / 2 + 255) / 256, 256>>>(ei);

    // CSR build (reused by both layers); scanA also computes dinv
    scanA_k<<<NBLK, 256>>>();
    scanB_k<<<1, 512>>>();
    scanC_k<<<NBLK, 256>>>();
    fill_k<<<(NE / 2 + 255) / 256, 256>>>(ei);

    gemm1_k<<<(NN + 127) / 128, 256>>>(x, W1);      // HMMA, 128-row tiles
    pull1_k<<<(NN * 32 + 255) / 256, 256>>>(b1);    // warp per node, 4-edge groups
    pull2_k<<<(NN * 32 + 255) / 256, 256>>>();

    gemm2mean_k<<<(NN + 127) / 128, 256>>>(W2, b2); // HMMA + fused mean
    fc_k<<<1, 64>>>(fcW, fcb, out);
}